// round 6
// baseline (speedup 1.0000x reference)
#include <cuda_runtime.h>
#include <cstdint>

#define NN      131071
#define NSTEPS  335
#define QLB     1e-4f
#define DTc     3600.0f
#define FULLM   0xFFFFFFFFu

// doorbells: flag(high 32) | float bits(low 32), one word per (step, node)
__device__ unsigned long long g1[NSTEPS * 4096];  // level-4 roots
__device__ unsigned long long g2[NSTEPS * 256];   // level-8 roots
__device__ unsigned long long g3[NSTEPS * 16];    // level-12 roots

__global__ void init_kernel() {
    int i = blockIdx.x * blockDim.x + threadIdx.x;
    if (i < NSTEPS * 4096) g1[i] = 0ull;
    if (i < NSTEPS * 256)  g2[i] = 0ull;
    if (i < NSTEPS * 16)   g3[i] = 0ull;
}

struct NodeC {
    float A_coef, pexp, inv_ns, wet_c, tw, ssx2, a1len, a2len;
};

__device__ __forceinline__ NodeC make_node(int g,
    const float* __restrict__ nr,  const float* __restrict__ qsr,
    const float* __restrict__ len, const float* __restrict__ slope,
    const float* __restrict__ twp, const float* __restrict__ ssp,
    const float* __restrict__ xp)
{
    NodeC c;
    float n  = fmaf(nr[g], 0.34f, 0.01f);
    float qs = 3.0f * qsr[g];
    float s0 = fmaxf(slope[g], 1e-4f);
    float sq = sqrtf(s0);
    float den = fmaf(21.0f, sq, 1e-8f);
    c.A_coef = n * (qs + 1.0f) / den;
    c.pexp   = 3.0f / fmaf(3.0f, qs, 5.0f);
    c.inv_ns = sq / n;
    float ssv = ssp[g];
    c.wet_c  = 2.0f * sqrtf(fmaf(ssv, ssv, 1.0f));
    c.tw     = twp[g];
    c.ssx2   = 2.0f * ssv;
    float L  = len[g];
    float xv = xp[g];
    c.a1len = 2.0f * (1.0f - xv) * L;
    c.a2len = 2.0f * xv * L;
    return c;
}

// r = 1/(DT*v + a1len);  c1=(DTv-a2len)r; c2=(DTv+a2len)r; c4=2DTv*r; c3=1-c4
__device__ __forceinline__ void phase_a(const NodeC& c, float q, float it, float qpc,
                                        float& b, float& c1)
{
    float depth  = fmaxf(__powf(q * c.A_coef, c.pexp), 0.01f);
    float bottom = fmaxf(fmaf(-c.ssx2, depth, c.tw), 0.1f);
    float area   = (c.tw + bottom) * depth * 0.5f;
    float wetted = fmaf(depth, c.wet_c, bottom);
    float R      = __fdividef(area, wetted);
    float v      = c.inv_ns * __powf(R, 0.66666668f);
    v = fminf(fmaxf(v, 0.3f), 15.0f) * (5.0f / 3.0f);
    float dv = DTc * v;
    float r  = __fdividef(1.0f, dv + c.a1len);
    c1       = (dv - c.a2len) * r;
    float c2 = (dv + c.a2len) * r;
    float c4 = (2.0f * dv) * r;
    float c3 = 1.0f - c4;
    b = fmaf(c2, it, fmaf(c3, q, c4 * qpc));
}

// One warp per block (grid=4369) for near-uniform per-SM load (30 vs 29 warps).
// Warp tiers: T1 levels 0-4 (4096 warps), T2 levels 5-8 (256), T3 levels 9-12 (16),
// T4 levels 13-16 (1). 15 internal nodes on lanes 0-14 (T1: +16 leaves on lanes
// 15-30); lanes 16-31 of T2..T4 poll the 16 child roots via acquire loads.
__global__ void __launch_bounds__(32, 30)
route_kernel(const float* __restrict__ qp,
             const float* __restrict__ nr,  const float* __restrict__ qsr,
             const float* __restrict__ len, const float* __restrict__ slope,
             const float* __restrict__ twp, const float* __restrict__ ssp,
             const float* __restrict__ xp,  float* __restrict__ out)
{
    const int w    = blockIdx.x;
    const int lane = threadIdx.x;

    int tier, sub;
    if      (w >= 273) { tier = 1; sub = w - 273; }
    else if (w >= 17)  { tier = 2; sub = w - 17;  }
    else if (w >= 1)   { tier = 3; sub = w - 1;   }
    else               { tier = 4; sub = 0;       }

    bool is_node, is_poll = false;
    int  gid = 0, mydepth = 9;
    int  sA, sB;
    unsigned long long* pollp = 0; int pollstride = 0;
    unsigned long long* pubp  = 0; int pubstride  = 0;

    if (tier == 1) {
        is_node = (lane < 31);
        if (is_node) {
            int dh = 31 - __clz(lane + 1);            // depth below subtree root, 0..4
            mydepth = dh;                              // leaves have dh==4
            gid = 131072 - (1 << (13 + dh)) + (sub << dh) + (lane + 1 - (1 << dh));
        }
        sA = min(2 * lane + 1, 31); sB = min(2 * lane + 2, 31);
        pubp = g1 + sub; pubstride = 4096;
    } else {
        is_node = (lane < 15);
        is_poll = (lane >= 16);
        const int bs = (tier == 2) ? 9 : (tier == 3) ? 5 : 1;
        if (is_node) {
            int dh = 31 - __clz(lane + 1);            // 0..3
            mydepth = dh;
            gid = 131072 - (1 << (bs + dh)) + (sub << dh) + (lane + 1 - (1 << dh));
        }
        // depth-3 nodes (lanes 7..14): children live on poll lanes 16..31
        if (lane >= 7 && lane <= 14) { sA = 2 * lane + 2; sB = 2 * lane + 3; }
        else { sA = min(2 * lane + 1, 31); sB = min(2 * lane + 2, 31); }
        const int c = lane - 16;
        if (tier == 2)      { pollp = g1 + sub * 16 + c; pollstride = 4096; pubp = g2 + sub; pubstride = 256; }
        else if (tier == 3) { pollp = g2 + sub * 16 + c; pollstride = 256;  pubp = g3 + sub; pubstride = 16;  }
        else                { pollp = g3 + c;            pollstride = 16; }
    }

    NodeC cN;
    float cq = 0.0f, qnext = 0.0f;
    if (is_node) {
        cN = make_node(gid, nr, qsr, len, slope, twp, ssp, xp);
        cq = qp[gid];                                  // q0 raw (no clamp)
        qnext = fmaxf(cq, QLB);                        // qpc for step 0
    }
    if (is_poll) {
        const int bs2 = (tier == 2) ? 13 : (tier == 3) ? 9 : 5;
        int cgid = 131072 - (1 << bs2) + sub * 16 + (lane - 16);
        cq = qp[cgid];                                 // child q0 raw
    }
    if (tier == 4 && lane == 0) out[0] = fmaxf(qp[NN - 1], QLB);

    for (int t = 0; t < NSTEPS; ++t) {
        float qpc = qnext;
        if (is_node) {                                 // prefetch next step's q_prime
            int tn = (t + 1 < NSTEPS) ? t + 1 : t;
            qnext = fmaxf(__ldg(qp + (size_t)tn * NN + gid), QLB);
        }
        // i_t from children's carry registers (previous-step q)
        float itA = __shfl_sync(FULLM, cq, sA);
        float itB = __shfl_sync(FULLM, cq, sB);
        float b = 0.0f, c1 = 0.0f;
        if (is_node) {
            float it = (mydepth == 4) ? 0.0f : (itA + itB);  // T1 leaves: no inflow
            phase_a(cN, cq, it, qpc, b, c1);
        }
        if (is_poll) {                                 // fetch this step's child root (raw)
            unsigned long long v;
            do {
                asm volatile("ld.acquire.gpu.global.b64 %0, [%1];"
                             : "=l"(v) : "l"(pollp) : "memory");
            } while ((v >> 32) == 0ull);
            b = __uint_as_float((unsigned)v);
            pollp += pollstride;
        }
        __syncwarp(FULLM);
        // bottom-up sweep on raw values, 4 levels, pure shuffles
        #pragma unroll
        for (int d = 3; d >= 0; --d) {
            float bl = __shfl_sync(FULLM, b, sA);
            float br = __shfl_sync(FULLM, b, sB);
            if (mydepth == d) b = fmaf(c1, bl + br, b);
        }
        if (lane == 0) {
            if (tier == 4) out[t + 1] = fmaxf(b, QLB);
            else {
                unsigned long long pv = (1ull << 32) | (unsigned long long)__float_as_uint(b);
                asm volatile("st.release.gpu.global.b64 [%0], %1;"
                             :: "l"(pubp), "l"(pv) : "memory");
                pubp += pubstride;
            }
        }
        cq = fmaxf(b, QLB);                            // carry (nodes) / child carry (pollers)
    }
}

extern "C" void kernel_launch(void* const* d_in, const int* in_sizes, int n_in,
                              void* d_out, int out_size)
{
    const float* qp    = (const float*)d_in[0];
    const float* nr    = (const float*)d_in[1];
    const float* qsr   = (const float*)d_in[2];
    const float* len   = (const float*)d_in[3];
    const float* slope = (const float*)d_in[4];
    const float* twp   = (const float*)d_in[5];
    const float* ssp   = (const float*)d_in[6];
    const float* xp    = (const float*)d_in[7];
    float* out = (float*)d_out;

    init_kernel<<<(NSTEPS * 4096 + 255) / 256, 256>>>();
    route_kernel<<<4369, 32>>>(qp, nr, qsr, len, slope, twp, ssp, xp, out);
}